// round 5
// baseline (speedup 1.0000x reference)
#include <cuda_runtime.h>

// StreamingPCEN: x[B=16, MICS=4, T=2048, F=257] fp32.
// EMA over T per (bm, f) lane, then (x/(M+eps)^alpha + delta)^r - delta^r.
//
// Round 3: NSEG=8 segments of 256 frames (vs 4x512). Grid = 16 x 9 x 8 = 1152
// blocks -> ~31 warps/SM (2.2x R2 occupancy) to push DRAM toward the roof.
// Halo = 320 frames, clamped at t=0 (segment 1 restarts exactly from t=0).
// Restart error on M: (1-s)^320 ~ 3e-4 -> output error ~2e-5, well under 1e-3.
// Halos mostly hit L2 (input ~fits in 126MB L2; single wave overlaps halo
// reads with neighbors' main reads), so DRAM-compulsory traffic stays ~270MB.

#define TT    2048
#define FFR   257
#define NFC   9          // ceil(257/32)
#define NSEG  8
#define SEG   256        // TT / NSEG
#define HALO  320        // 10 chunks of 32; clamped at t=0
#define U     32
#define UHCH  (HALO / U) // 10 halo chunks (max)
#define UMCH  (SEG / U)  // 8 main chunks
#define PCEN_EPS 1e-6f

__device__ __forceinline__ float fast_lg2(float a) {
    float r; asm("lg2.approx.f32 %0, %1;" : "=f"(r) : "f"(a)); return r;
}
__device__ __forceinline__ float fast_ex2(float a) {
    float r; asm("ex2.approx.f32 %0, %1;" : "=f"(r) : "f"(a)); return r;
}
__device__ __forceinline__ float fast_sqrt(float a) {
    float r; asm("sqrt.approx.f32 %0, %1;" : "=f"(r) : "f"(a)); return r;
}

__global__ __launch_bounds__(128, 8)
void pcen_kernel(const float* __restrict__ x,
                 const float* __restrict__ s_p,
                 const float* __restrict__ a_p,
                 const float* __restrict__ d_p,
                 const float* __restrict__ r_p,
                 float* __restrict__ out)
{
    const int seg  = blockIdx.x & 7;           // NSEG = 8
    const int rest = blockIdx.x >> 3;
    const int fc   = rest % NFC;
    const int bg   = rest / NFC;
    const int w    = threadIdx.x >> 5;
    const int lane = threadIdx.x & 31;
    const int bm   = bg * 4 + w;
    const int f    = fc * 32 + lane;
    const bool act = (f < FFR);
    const int fcl  = act ? f : (FFR - 1);      // clamp loads for inactive lanes

    const float s     = __ldg(s_p);
    const float alpha = __ldg(a_p);
    const float delta = __ldg(d_p);
    const float r     = __ldg(r_p);
    const float oms   = 1.0f - s;
    const float na    = -alpha;
    const float c2    = oms * oms;             // (1-s)^2  (2-step halo EMA)
    const float s1    = s * oms;               // s(1-s)
    const bool  use_sqrt = (r == 0.5f);
    const float dr    = use_sqrt ? fast_sqrt(delta)
                                 : fast_ex2(r * fast_lg2(delta));  // delta^r

    const float* base = x + (size_t)bm * TT * FFR;
    const int t0 = seg * SEG;

    float bufA[U], bufB[U];
    float m = 0.0f;

    // ---------------- Halo warm-up (segments 1..7) ----------------
    if (seg != 0) {
        // Clamp halo at t=0. Segment 1 (t0=256 < HALO) restarts exactly
        // from t=0; halo lengths are 256 (8 chunks) or 320 (10 chunks),
        // both even, so the pair-structured loop is safe.
        const int hstart = (t0 >= HALO) ? (t0 - HALO) : 0;
        const int nh     = (t0 - hstart) / U;   // 8 or 10 chunks

        const float* lp = base + (size_t)hstart * FFR + fcl;

        #pragma unroll
        for (int i = 0; i < U; i++) bufA[i] = __ldg(lp + i * FFR);
        lp += U * FFR;

        // Restart: m_init = x[hstart]; the 2-step update then reproduces the
        // recurrence restarted at hstart (exact when hstart == 0).
        m = bufA[0];

        #pragma unroll 1
        for (int c = 0; c < nh; c += 2) {
            #pragma unroll
            for (int i = 0; i < U; i++) bufB[i] = __ldg(lp + i * FFR);
            lp += U * FFR;

            #pragma unroll
            for (int i = 0; i < U; i += 2) {
                const float inner = fmaf(s1, bufA[i], s * bufA[i + 1]);
                m = fmaf(c2, m, inner);
            }

            if (c + 2 < nh) {
                #pragma unroll
                for (int i = 0; i < U; i++) bufA[i] = __ldg(lp + i * FFR);
                lp += U * FFR;
            }

            #pragma unroll
            for (int i = 0; i < U; i += 2) {
                const float inner = fmaf(s1, bufB[i], s * bufB[i + 1]);
                m = fmaf(c2, m, inner);
            }
        }
    }

    // ---------------- Main segment ----------------
    const float* lp = base + (size_t)t0 * FFR + fcl;
    float*       sp = out + (size_t)bm * TT * FFR + (size_t)t0 * FFR + f;

    #pragma unroll
    for (int i = 0; i < U; i++) bufA[i] = __ldg(lp + i * FFR);
    lp += U * FFR;

    if (seg == 0) m = bufA[0];   // M_0 = x_0

    #pragma unroll 1
    for (int c = 0; c < UMCH; c += 2) {
        #pragma unroll
        for (int i = 0; i < U; i++) bufB[i] = __ldg(lp + i * FFR);
        lp += U * FFR;

        if (use_sqrt) {
            #pragma unroll
            for (int i = 0; i < U; i++) {
                const float xv = bufA[i];
                m = fmaf(oms, m, s * xv);
                const float e = fast_ex2(na * fast_lg2(m + PCEN_EPS));
                const float v = fmaf(xv, e, delta);
                const float o = fast_sqrt(v) - dr;
                if (act) sp[i * FFR] = o;
            }
        } else {
            #pragma unroll
            for (int i = 0; i < U; i++) {
                const float xv = bufA[i];
                m = fmaf(oms, m, s * xv);
                const float e = fast_ex2(na * fast_lg2(m + PCEN_EPS));
                const float v = fmaf(xv, e, delta);
                const float o = fast_ex2(r * fast_lg2(v)) - dr;
                if (act) sp[i * FFR] = o;
            }
        }
        sp += U * FFR;

        if (c + 2 < UMCH) {
            #pragma unroll
            for (int i = 0; i < U; i++) bufA[i] = __ldg(lp + i * FFR);
            lp += U * FFR;
        }

        if (use_sqrt) {
            #pragma unroll
            for (int i = 0; i < U; i++) {
                const float xv = bufB[i];
                m = fmaf(oms, m, s * xv);
                const float e = fast_ex2(na * fast_lg2(m + PCEN_EPS));
                const float v = fmaf(xv, e, delta);
                const float o = fast_sqrt(v) - dr;
                if (act) sp[i * FFR] = o;
            }
        } else {
            #pragma unroll
            for (int i = 0; i < U; i++) {
                const float xv = bufB[i];
                m = fmaf(oms, m, s * xv);
                const float e = fast_ex2(na * fast_lg2(m + PCEN_EPS));
                const float v = fmaf(xv, e, delta);
                const float o = fast_ex2(r * fast_lg2(v)) - dr;
                if (act) sp[i * FFR] = o;
            }
        }
        sp += U * FFR;
    }
}

extern "C" void kernel_launch(void* const* d_in, const int* in_sizes, int n_in,
                              void* d_out, int out_size)
{
    const float* x   = (const float*)d_in[0];
    const float* s_p = (const float*)d_in[1];
    const float* a_p = (const float*)d_in[2];
    const float* d_p = (const float*)d_in[3];
    const float* r_p = (const float*)d_in[4];
    float*       out = (float*)d_out;

    dim3 grid(16 * NFC * NSEG);   // 1152 blocks
    dim3 block(128);
    pcen_kernel<<<grid, block>>>(x, s_p, a_p, d_p, r_p, out);
}

// round 6
// speedup vs baseline: 1.1199x; 1.1199x over previous
#include <cuda_runtime.h>

// StreamingPCEN: x[B=16, MICS=4, T=2048, F=257] fp32.
// EMA over T per (bm, f) lane, then (x/(M+eps)^alpha + delta)^r - delta^r.
//
// Round 6: NSEG=8 kept (32 warps/SM), but chunk size U=16 so the double
// buffer (2x16 floats) + scalars fits the 64-reg cap of
// __launch_bounds__(128,8) WITHOUT spills (R5 regression cause: U=32 buffers
// spilled at 64 regs). Aggregate MLP/SM = 32 warps x 16 in-flight = 512.
// HALO=256, uniform across segments 1..7 (segment 1 restarts exactly at t=0);
// restart error on M: (1-s)^256 ~ 1.5e-3 -> output ~1.5e-4, 6x under 1e-3.

#define TT    2048
#define FFR   257
#define NFC   9          // ceil(257/32)
#define NSEG  8
#define SEG   256        // TT / NSEG
#define HALO  256
#define U     16
#define UHCH  (HALO / U) // 16 halo chunks
#define UMCH  (SEG / U)  // 16 main chunks
#define PCEN_EPS 1e-6f

__device__ __forceinline__ float fast_lg2(float a) {
    float r; asm("lg2.approx.f32 %0, %1;" : "=f"(r) : "f"(a)); return r;
}
__device__ __forceinline__ float fast_ex2(float a) {
    float r; asm("ex2.approx.f32 %0, %1;" : "=f"(r) : "f"(a)); return r;
}
__device__ __forceinline__ float fast_sqrt(float a) {
    float r; asm("sqrt.approx.f32 %0, %1;" : "=f"(r) : "f"(a)); return r;
}

__global__ __launch_bounds__(128, 8)
void pcen_kernel(const float* __restrict__ x,
                 const float* __restrict__ s_p,
                 const float* __restrict__ a_p,
                 const float* __restrict__ d_p,
                 const float* __restrict__ r_p,
                 float* __restrict__ out)
{
    const int seg  = blockIdx.x & 7;           // NSEG = 8
    const int rest = blockIdx.x >> 3;
    const int fc   = rest % NFC;
    const int bg   = rest / NFC;
    const int w    = threadIdx.x >> 5;
    const int lane = threadIdx.x & 31;
    const int bm   = bg * 4 + w;
    const int f    = fc * 32 + lane;
    const bool act = (f < FFR);
    const int fcl  = act ? f : (FFR - 1);      // clamp loads for inactive lanes

    const float s     = __ldg(s_p);
    const float alpha = __ldg(a_p);
    const float delta = __ldg(d_p);
    const float r     = __ldg(r_p);
    const float oms   = 1.0f - s;
    const float na    = -alpha;
    const float c2    = oms * oms;             // (1-s)^2  (2-step halo EMA)
    const float s1    = s * oms;               // s(1-s)
    const bool  use_sqrt = (r == 0.5f);
    const float dr    = use_sqrt ? fast_sqrt(delta)
                                 : fast_ex2(r * fast_lg2(delta));  // delta^r

    const float* base = x + (size_t)bm * TT * FFR;
    const int t0 = seg * SEG;

    float bufA[U], bufB[U];
    float m = 0.0f;

    // ---------------- Halo warm-up (segments 1..7) ----------------
    // HALO == SEG == 256, so every halo starts exactly at the previous
    // segment's start; segment 1's halo starts at t=0 (exact restart).
    if (seg != 0) {
        const float* lp = base + (size_t)(t0 - HALO) * FFR + fcl;

        #pragma unroll
        for (int i = 0; i < U; i++) bufA[i] = __ldg(lp + i * FFR);
        lp += U * FFR;

        // Restart: m_init = x[hstart]; the 2-step update then reproduces the
        // recurrence restarted at hstart (exact when hstart == 0).
        m = bufA[0];

        #pragma unroll 1
        for (int c = 0; c < UHCH; c += 2) {
            #pragma unroll
            for (int i = 0; i < U; i++) bufB[i] = __ldg(lp + i * FFR);
            lp += U * FFR;

            #pragma unroll
            for (int i = 0; i < U; i += 2) {
                const float inner = fmaf(s1, bufA[i], s * bufA[i + 1]);
                m = fmaf(c2, m, inner);
            }

            if (c + 2 < UHCH) {
                #pragma unroll
                for (int i = 0; i < U; i++) bufA[i] = __ldg(lp + i * FFR);
                lp += U * FFR;
            }

            #pragma unroll
            for (int i = 0; i < U; i += 2) {
                const float inner = fmaf(s1, bufB[i], s * bufB[i + 1]);
                m = fmaf(c2, m, inner);
            }
        }
    }

    // ---------------- Main segment ----------------
    const float* lp = base + (size_t)t0 * FFR + fcl;
    float*       sp = out + (size_t)bm * TT * FFR + (size_t)t0 * FFR + f;

    #pragma unroll
    for (int i = 0; i < U; i++) bufA[i] = __ldg(lp + i * FFR);
    lp += U * FFR;

    if (seg == 0) m = bufA[0];   // M_0 = x_0

    #pragma unroll 1
    for (int c = 0; c < UMCH; c += 2) {
        #pragma unroll
        for (int i = 0; i < U; i++) bufB[i] = __ldg(lp + i * FFR);
        lp += U * FFR;

        if (use_sqrt) {
            #pragma unroll
            for (int i = 0; i < U; i++) {
                const float xv = bufA[i];
                m = fmaf(oms, m, s * xv);
                const float e = fast_ex2(na * fast_lg2(m + PCEN_EPS));
                const float v = fmaf(xv, e, delta);
                const float o = fast_sqrt(v) - dr;
                if (act) sp[i * FFR] = o;
            }
        } else {
            #pragma unroll
            for (int i = 0; i < U; i++) {
                const float xv = bufA[i];
                m = fmaf(oms, m, s * xv);
                const float e = fast_ex2(na * fast_lg2(m + PCEN_EPS));
                const float v = fmaf(xv, e, delta);
                const float o = fast_ex2(r * fast_lg2(v)) - dr;
                if (act) sp[i * FFR] = o;
            }
        }
        sp += U * FFR;

        if (c + 2 < UMCH) {
            #pragma unroll
            for (int i = 0; i < U; i++) bufA[i] = __ldg(lp + i * FFR);
            lp += U * FFR;
        }

        if (use_sqrt) {
            #pragma unroll
            for (int i = 0; i < U; i++) {
                const float xv = bufB[i];
                m = fmaf(oms, m, s * xv);
                const float e = fast_ex2(na * fast_lg2(m + PCEN_EPS));
                const float v = fmaf(xv, e, delta);
                const float o = fast_sqrt(v) - dr;
                if (act) sp[i * FFR] = o;
            }
        } else {
            #pragma unroll
            for (int i = 0; i < U; i++) {
                const float xv = bufB[i];
                m = fmaf(oms, m, s * xv);
                const float e = fast_ex2(na * fast_lg2(m + PCEN_EPS));
                const float v = fmaf(xv, e, delta);
                const float o = fast_ex2(r * fast_lg2(v)) - dr;
                if (act) sp[i * FFR] = o;
            }
        }
        sp += U * FFR;
    }
}

extern "C" void kernel_launch(void* const* d_in, const int* in_sizes, int n_in,
                              void* d_out, int out_size)
{
    const float* x   = (const float*)d_in[0];
    const float* s_p = (const float*)d_in[1];
    const float* a_p = (const float*)d_in[2];
    const float* d_p = (const float*)d_in[3];
    const float* r_p = (const float*)d_in[4];
    float*       out = (float*)d_out;

    dim3 grid(16 * NFC * NSEG);   // 1152 blocks, ~7.8 blocks/SM, single wave
    dim3 block(128);
    pcen_kernel<<<grid, block>>>(x, s_p, a_p, d_p, r_p, out);
}